// round 5
// baseline (speedup 1.0000x reference)
#include <cuda_runtime.h>
#include <cuda_bf16.h>
#include <math.h>
#include <stdint.h>

#define TOKS    16384
#define NEXP    256
#define KDIM    7168
#define BM      128
#define BN      64
#define BK      64
#define NCH     (KDIM / BK)     // 112
#define THREADS 256

__device__ __align__(16) float g_logits[(size_t)TOKS * NEXP];
__device__ __align__(16) __nv_bfloat16 g_Blimb[3][(size_t)NEXP * KDIM];

// ---- smem layout (bytes), all bf16 with 144B (72 bf16) row stride ----------
// A segs: (L*2+buf)*18432 + row*144 + k*2        rows 0..127   [0, 110592)
// B segs: 110592 + (L*2+buf)*9216 + row*144 + k*2  rows 0..63  [110592, 165888)
#define SA_SEG   18432
#define SB_BASE  110592
#define SB_SEG   9216
#define SMEM_BYTES 165888

__device__ __forceinline__ uint32_t smem_u32(const void* p) {
    uint32_t a;
    asm("{ .reg .u64 t; cvta.to.shared.u64 t, %1; cvt.u32.u64 %0, t; }" : "=r"(a) : "l"(p));
    return a;
}
__device__ __forceinline__ void cp_async16(uint32_t sdst, const void* gsrc) {
    asm volatile("cp.async.cg.shared.global [%0], [%1], 16;" :: "r"(sdst), "l"(gsrc));
}
#define CP_COMMIT() asm volatile("cp.async.commit_group;" ::: "memory")
#define CP_WAIT0()  asm volatile("cp.async.wait_group 0;" ::: "memory")

__device__ __forceinline__ void mma16816(float d[4],
                                         uint32_t a0, uint32_t a1, uint32_t a2, uint32_t a3,
                                         uint32_t b0, uint32_t b1) {
    asm volatile(
        "mma.sync.aligned.m16n8k16.row.col.f32.bf16.bf16.f32 "
        "{%0,%1,%2,%3}, {%4,%5,%6,%7}, {%8,%9}, {%0,%1,%2,%3};"
        : "+f"(d[0]), "+f"(d[1]), "+f"(d[2]), "+f"(d[3])
        : "r"(a0), "r"(a1), "r"(a2), "r"(a3), "r"(b0), "r"(b1));
}

// split a pair of fp32 (k, k+1) into 3 packed bf16x2 limbs (lo = first elem)
__device__ __forceinline__ void split_pair(float v0, float v1,
                                           uint32_t& h, uint32_t& m, uint32_t& l) {
    asm("cvt.rn.bf16x2.f32 %0, %1, %2;" : "=r"(h) : "f"(v1), "f"(v0));
    float h0 = __uint_as_float(h << 16);
    float h1 = __uint_as_float(h & 0xffff0000u);
    float r0 = v0 - h0, r1 = v1 - h1;
    asm("cvt.rn.bf16x2.f32 %0, %1, %2;" : "=r"(m) : "f"(r1), "f"(r0));
    float m0 = __uint_as_float(m << 16);
    float m1 = __uint_as_float(m & 0xffff0000u);
    r0 -= m0; r1 -= m1;
    asm("cvt.rn.bf16x2.f32 %0, %1, %2;" : "=r"(l) : "f"(r1), "f"(r0));
}

// ---------------------------------------------------------------------------
// B limb pre-conversion
// ---------------------------------------------------------------------------
__global__ void gate_bconv_kernel(const float* __restrict__ W) {
    int i = blockIdx.x * blockDim.x + threadIdx.x;
    if (i >= NEXP * KDIM) return;
    float v = W[i];
    __nv_bfloat16 h = __float2bfloat16_rn(v);
    float r1 = v - __bfloat162float(h);
    __nv_bfloat16 m = __float2bfloat16_rn(r1);
    float r2 = r1 - __bfloat162float(m);
    g_Blimb[0][i] = h;
    g_Blimb[1][i] = m;
    g_Blimb[2][i] = __float2bfloat16_rn(r2);
}

// ---------------------------------------------------------------------------
// mma.sync bf16 3-limb GEMM: logits[t,n] = x[t,:] . W[n,:]
// ---------------------------------------------------------------------------
__global__ __launch_bounds__(THREADS, 1)
void gate_mma_gemm(const float* __restrict__ X) {
    extern __shared__ char smem[];
    const uint32_t sbu = smem_u32(smem);

    const int tid  = threadIdx.x;
    const int lane = tid & 31;
    const int wid  = tid >> 5;
    const int wm   = wid & 3;        // warp row 0..3  (32 tokens each)
    const int wn   = wid >> 2;       // warp col 0..1  (32 experts each)
    const int g    = lane >> 2;
    const int t    = lane & 3;

    const int bn = blockIdx.x;
    const int bm = blockIdx.y;
    const int t0 = bm * BM;
    const int n0 = bn * BN;

    // A gmem loader: thread -> (row, 32-k half)
    const int arow = tid >> 1;
    const int akh  = (tid & 1) * 32;
    const float* agp = X + (size_t)(t0 + arow) * KDIM + akh;
    const uint32_t asts = (uint32_t)arow * 144 + (uint32_t)akh * 2;

    float acc_hh[2][4][4], acc_cr[2][4][4], tot[2][4][4];
    #pragma unroll
    for (int i = 0; i < 2; i++)
        #pragma unroll
        for (int j = 0; j < 4; j++)
            #pragma unroll
            for (int q = 0; q < 4; q++) {
                acc_hh[i][j][q] = 0.0f; acc_cr[i][j][q] = 0.0f; tot[i][j][q] = 0.0f;
            }

    float4 af[8];

    // ---- helpers as macros via lambdas ----
    auto load_a_regs = [&](int kt) {
        const float4* p = (const float4*)(agp + kt * BK);
        #pragma unroll
        for (int i = 0; i < 8; i++) af[i] = p[i];
    };
    auto issue_b = [&](int kt, int buf) {
        #pragma unroll
        for (int L = 0; L < 3; L++) {
            const __nv_bfloat16* gB = g_Blimb[L] + (size_t)n0 * KDIM + kt * BK;
            uint32_t sB = sbu + SB_BASE + (uint32_t)(L * 2 + buf) * SB_SEG;
            #pragma unroll
            for (int q = 0; q < 2; q++) {
                int line = q * 256 + tid;
                int row  = line >> 3, c = line & 7;
                cp_async16(sB + (uint32_t)row * 144 + (uint32_t)c * 16,
                           gB + (size_t)row * KDIM + c * 8);
            }
        }
    };
    auto sts_a = [&](int buf) {
        const float* v = (const float*)af;
        uint32_t ph[16], pm[16], pl[16];
        #pragma unroll
        for (int i = 0; i < 16; i++)
            split_pair(v[2 * i], v[2 * i + 1], ph[i], pm[i], pl[i]);
        uint32_t base = asts;
        char* s0 = smem + (0 * 2 + buf) * SA_SEG;
        char* s1 = smem + (1 * 2 + buf) * SA_SEG;
        char* s2 = smem + (2 * 2 + buf) * SA_SEG;
        #pragma unroll
        for (int c = 0; c < 4; c++) {
            uint32_t off = base + (uint32_t)c * 16;
            *(uint4*)(s0 + off) = make_uint4(ph[4*c], ph[4*c+1], ph[4*c+2], ph[4*c+3]);
            *(uint4*)(s1 + off) = make_uint4(pm[4*c], pm[4*c+1], pm[4*c+2], pm[4*c+3]);
            *(uint4*)(s2 + off) = make_uint4(pl[4*c], pl[4*c+1], pl[4*c+2], pl[4*c+3]);
        }
    };

    // ---- prologue: chunk 0 ----
    load_a_regs(0);
    issue_b(0, 0);
    CP_COMMIT();
    sts_a(0);
    CP_WAIT0();
    __syncthreads();

    for (int kt = 0; kt < NCH; kt++) {
        const int buf = kt & 1;
        if (kt + 1 < NCH) {
            load_a_regs(kt + 1);
            issue_b(kt + 1, 1 - buf);
            CP_COMMIT();
        }

        // ---- compute on buf ----
        const char* sA0 = smem + (0 * 2 + buf) * SA_SEG;
        const char* sA1 = smem + (1 * 2 + buf) * SA_SEG;
        const char* sA2 = smem + (2 * 2 + buf) * SA_SEG;
        const char* sB0 = smem + SB_BASE + (0 * 2 + buf) * SB_SEG;
        const char* sB1 = smem + SB_BASE + (1 * 2 + buf) * SB_SEG;
        const char* sB2 = smem + SB_BASE + (2 * 2 + buf) * SB_SEG;

        #pragma unroll
        for (int ks = 0; ks < 4; ks++) {
            const uint32_t kb0 = (uint32_t)(ks * 16 + 2 * t) * 2;  // byte off of pair
            const uint32_t kb1 = kb0 + 16;

            uint32_t Ah[2][4], Am[2][4], Al[2][4];
            #pragma unroll
            for (int m2 = 0; m2 < 2; m2++) {
                const uint32_t r0 = (uint32_t)(wm * 32 + m2 * 16 + g) * 144;
                const uint32_t r8 = r0 + 8 * 144;
                Ah[m2][0] = *(const uint32_t*)(sA0 + r0 + kb0);
                Ah[m2][1] = *(const uint32_t*)(sA0 + r8 + kb0);
                Ah[m2][2] = *(const uint32_t*)(sA0 + r0 + kb1);
                Ah[m2][3] = *(const uint32_t*)(sA0 + r8 + kb1);
                Am[m2][0] = *(const uint32_t*)(sA1 + r0 + kb0);
                Am[m2][1] = *(const uint32_t*)(sA1 + r8 + kb0);
                Am[m2][2] = *(const uint32_t*)(sA1 + r0 + kb1);
                Am[m2][3] = *(const uint32_t*)(sA1 + r8 + kb1);
                Al[m2][0] = *(const uint32_t*)(sA2 + r0 + kb0);
                Al[m2][1] = *(const uint32_t*)(sA2 + r8 + kb0);
                Al[m2][2] = *(const uint32_t*)(sA2 + r0 + kb1);
                Al[m2][3] = *(const uint32_t*)(sA2 + r8 + kb1);
            }
            uint32_t Bh[4][2], Bm[4][2], Bl[4][2];
            #pragma unroll
            for (int n4 = 0; n4 < 4; n4++) {
                const uint32_t rn = (uint32_t)(wn * 32 + n4 * 8 + g) * 144;
                Bh[n4][0] = *(const uint32_t*)(sB0 + rn + kb0);
                Bh[n4][1] = *(const uint32_t*)(sB0 + rn + kb1);
                Bm[n4][0] = *(const uint32_t*)(sB1 + rn + kb0);
                Bm[n4][1] = *(const uint32_t*)(sB1 + rn + kb1);
                Bl[n4][0] = *(const uint32_t*)(sB2 + rn + kb0);
                Bl[n4][1] = *(const uint32_t*)(sB2 + rn + kb1);
            }
            #pragma unroll
            for (int m2 = 0; m2 < 2; m2++) {
                #pragma unroll
                for (int n4 = 0; n4 < 4; n4++) {
                    mma16816(acc_hh[m2][n4], Ah[m2][0], Ah[m2][1], Ah[m2][2], Ah[m2][3],
                             Bh[n4][0], Bh[n4][1]);
                    mma16816(acc_cr[m2][n4], Ah[m2][0], Ah[m2][1], Ah[m2][2], Ah[m2][3],
                             Bm[n4][0], Bm[n4][1]);
                    mma16816(acc_cr[m2][n4], Am[m2][0], Am[m2][1], Am[m2][2], Am[m2][3],
                             Bh[n4][0], Bh[n4][1]);
                    mma16816(acc_cr[m2][n4], Am[m2][0], Am[m2][1], Am[m2][2], Am[m2][3],
                             Bm[n4][0], Bm[n4][1]);
                    mma16816(acc_cr[m2][n4], Ah[m2][0], Ah[m2][1], Ah[m2][2], Ah[m2][3],
                             Bl[n4][0], Bl[n4][1]);
                    mma16816(acc_cr[m2][n4], Al[m2][0], Al[m2][1], Al[m2][2], Al[m2][3],
                             Bh[n4][0], Bh[n4][1]);
                }
            }
        }

        if (kt + 1 < NCH) sts_a(1 - buf);
        CP_WAIT0();
        __syncthreads();

        if ((kt & 31) == 31) {   // flush hh accumulators (bounds serial error)
            #pragma unroll
            for (int m2 = 0; m2 < 2; m2++)
                #pragma unroll
                for (int n4 = 0; n4 < 4; n4++)
                    #pragma unroll
                    for (int q = 0; q < 4; q++) {
                        tot[m2][n4][q] += acc_hh[m2][n4][q];
                        acc_hh[m2][n4][q] = 0.0f;
                    }
        }
    }

    // ---- epilogue ----
    #pragma unroll
    for (int m2 = 0; m2 < 2; m2++) {
        #pragma unroll
        for (int n4 = 0; n4 < 4; n4++) {
            float f0 = (tot[m2][n4][0] + acc_hh[m2][n4][0]) + acc_cr[m2][n4][0];
            float f1 = (tot[m2][n4][1] + acc_hh[m2][n4][1]) + acc_cr[m2][n4][1];
            float f2 = (tot[m2][n4][2] + acc_hh[m2][n4][2]) + acc_cr[m2][n4][2];
            float f3 = (tot[m2][n4][3] + acc_hh[m2][n4][3]) + acc_cr[m2][n4][3];
            const int row = t0 + wm * 32 + m2 * 16 + g;
            const int col = n0 + wn * 32 + n4 * 8 + 2 * t;
            *(float2*)(g_logits + (size_t)row * NEXP + col)       = make_float2(f0, f1);
            *(float2*)(g_logits + (size_t)(row + 8) * NEXP + col) = make_float2(f2, f3);
        }
    }
}

// ---------------------------------------------------------------------------
// Routing: one warp per token (validated in rounds 2-3)
// ---------------------------------------------------------------------------
__global__ void gate_route_kernel(const float* __restrict__ bias,
                                  float* __restrict__ out_w,
                                  float* __restrict__ out_i,
                                  int Tn) {
    const int warp = (blockIdx.x * blockDim.x + threadIdx.x) >> 5;
    if (warp >= Tn) return;
    const int lane = threadIdx.x & 31;
    const unsigned FULL = 0xffffffffu;

    const float* row = g_logits + (size_t)warp * NEXP;
    float4 v0 = *(const float4*)(row + lane * 8);
    float4 v1 = *(const float4*)(row + lane * 8 + 4);
    float zz[8] = {v0.x, v0.y, v0.z, v0.w, v1.x, v1.y, v1.z, v1.w};

    float sc[8], sb8[8];
    #pragma unroll
    for (int j = 0; j < 8; j++) {
        float s = 1.0f / (1.0f + expf(-zz[j]));
        sc[j]  = s;
        sb8[j] = s + bias[lane * 8 + j];
    }

    float m1 = -INFINITY, m2 = -INFINITY;
    #pragma unroll
    for (int j = 0; j < 8; j++) {
        float v = sb8[j];
        if (v > m1) { m2 = m1; m1 = v; }
        else if (v > m2) { m2 = v; }
    }
    #pragma unroll
    for (int off = 1; off <= 2; off <<= 1) {
        float o1 = __shfl_xor_sync(FULL, m1, off);
        float o2 = __shfl_xor_sync(FULL, m2, off);
        if (o1 > m1) { m2 = fmaxf(m1, o2); m1 = o1; }
        else         { m2 = fmaxf(m2, o1); }
    }
    float gsum = m1 + m2;

    float gs[8];
    #pragma unroll
    for (int gI = 0; gI < 8; gI++) gs[gI] = __shfl_sync(FULL, gsum, gI * 4);

    int chosen = 0;
    #pragma unroll
    for (int it = 0; it < 4; it++) {
        float best = -INFINITY; int bg = 0;
        #pragma unroll
        for (int gI = 0; gI < 8; gI++) {
            if (!((chosen >> gI) & 1) && gs[gI] > best) { best = gs[gI]; bg = gI; }
        }
        chosen |= 1 << bg;
    }
    const bool kept = (chosen >> (lane >> 2)) & 1;

    float v[8];
    #pragma unroll
    for (int j = 0; j < 8; j++) v[j] = kept ? sb8[j] : -INFINITY;

    float my_w = 0.0f; int my_i = 0;
    float wsum = 0.0f;

    #pragma unroll
    for (int it = 0; it < 8; it++) {
        float bv = -INFINITY; int bi = 0x7fffffff; float bsco = 0.0f;
        #pragma unroll
        for (int j = 0; j < 8; j++) {
            if (v[j] > bv) { bv = v[j]; bi = lane * 8 + j; bsco = sc[j]; }
        }
        #pragma unroll
        for (int off = 16; off; off >>= 1) {
            float ov = __shfl_xor_sync(FULL, bv, off);
            int   oi = __shfl_xor_sync(FULL, bi, off);
            float os = __shfl_xor_sync(FULL, bsco, off);
            if (ov > bv || (ov == bv && oi < bi)) { bv = ov; bi = oi; bsco = os; }
        }
        if (lane == it) { my_w = bsco; my_i = bi; }
        if ((bi >> 3) == lane) v[bi & 7] = -INFINITY;
        wsum += bsco;
    }

    if (lane < 8) {
        out_w[(size_t)warp * 8 + lane] = (my_w / wsum) * 2.5f;
        out_i[(size_t)warp * 8 + lane] = (float)my_i;
    }
}

// ---------------------------------------------------------------------------
extern "C" void kernel_launch(void* const* d_in, const int* in_sizes, int n_in,
                              void* d_out, int out_size) {
    const float* x    = (const float*)d_in[0];   // [T, 7168]
    const float* w    = (const float*)d_in[1];   // [256, 7168]
    const float* bias = (const float*)d_in[2];   // [256]

    const int Tn = in_sizes[0] / KDIM;

    cudaFuncSetAttribute(gate_mma_gemm,
                         cudaFuncAttributeMaxDynamicSharedMemorySize, SMEM_BYTES);

    gate_bconv_kernel<<<(NEXP * KDIM + 255) / 256, 256>>>(w);

    dim3 grid(NEXP / BN, Tn / BM);   // (4, 128), bn fastest -> x L2 reuse
    gate_mma_gemm<<<grid, THREADS, SMEM_BYTES>>>(x);

    float* out_w = (float*)d_out;
    float* out_i = (float*)d_out + (size_t)Tn * 8;
    const int warps_per_block = 8;
    const int blocks = (Tn + warps_per_block - 1) / warps_per_block;
    gate_route_kernel<<<blocks, warps_per_block * 32>>>(bias, out_w, out_i, Tn);
}